// round 1
// baseline (speedup 1.0000x reference)
#include <cuda_runtime.h>
#include <math.h>

#define D_MODEL 1024
#define D_FF    4096
#define N_EXP   8
#define T_TOK   4096
#define H_ROWS  (T_TOK * 2 + 128)   // 8192 slots + tile padding

// ---- scratch (__device__ globals: no cudaMalloc allowed) ----
__device__ int   g_count[N_EXP];
__device__ int   g_off[N_EXP + 1];
__device__ int   g_rows[N_EXP * T_TOK];
__device__ float g_gate[N_EXP * T_TOK];
__device__ float g_H[(size_t)H_ROWS * D_FF];   // ~136 MB

// ---------------------------------------------------------------------------
__global__ void zero_counts_kernel() {
    if (threadIdx.x < N_EXP) g_count[threadIdx.x] = 0;
}

// one warp per token: logits, top-2, gates, scatter into per-expert lists
__global__ void router_kernel(const float* __restrict__ x,
                              const float* __restrict__ Wr) {
    int tok  = (blockIdx.x * blockDim.x + threadIdx.x) >> 5;
    int lane = threadIdx.x & 31;
    if (tok >= T_TOK) return;
    const float* xr = x + (size_t)tok * D_MODEL;

    float acc[N_EXP];
#pragma unroll
    for (int e = 0; e < N_EXP; e++) acc[e] = 0.f;

    for (int d = lane; d < D_MODEL; d += 32) {
        float xv = xr[d];
        float4 w0 = *(const float4*)(Wr + (size_t)d * N_EXP);
        float4 w1 = *(const float4*)(Wr + (size_t)d * N_EXP + 4);
        acc[0] += xv * w0.x; acc[1] += xv * w0.y;
        acc[2] += xv * w0.z; acc[3] += xv * w0.w;
        acc[4] += xv * w1.x; acc[5] += xv * w1.y;
        acc[6] += xv * w1.z; acc[7] += xv * w1.w;
    }
#pragma unroll
    for (int e = 0; e < N_EXP; e++) {
#pragma unroll
        for (int o = 16; o > 0; o >>= 1)
            acc[e] += __shfl_xor_sync(0xffffffffu, acc[e], o);
    }
    if (lane == 0) {
        int e1 = 0; float l1 = acc[0];
#pragma unroll
        for (int e = 1; e < N_EXP; e++)
            if (acc[e] > l1) { l1 = acc[e]; e1 = e; }
        int e2 = (e1 == 0) ? 1 : 0; float l2 = acc[e2];
#pragma unroll
        for (int e = 0; e < N_EXP; e++)
            if (e != e1 && acc[e] > l2) { l2 = acc[e]; e2 = e; }
        // softmax normalization cancels: gate1 = p1/(p1+p2) = 1/(1+exp(l2-l1))
        float g1 = 1.f / (1.f + expf(l2 - l1));
        float g2 = 1.f - g1;
        int p1 = atomicAdd(&g_count[e1], 1);
        g_rows[e1 * T_TOK + p1] = tok;
        g_gate[e1 * T_TOK + p1] = g1;
        int p2 = atomicAdd(&g_count[e2], 1);
        g_rows[e2 * T_TOK + p2] = tok;
        g_gate[e2 * T_TOK + p2] = g2;
    }
}

__global__ void offsets_kernel() {
    if (threadIdx.x == 0) {
        int s = 0;
        for (int e = 0; e < N_EXP; e++) { g_off[e] = s; s += g_count[e]; }
        g_off[N_EXP] = s;
    }
}

// ---------------------------------------------------------------------------
// Pass A:  H = relu( X[gathered rows] @ W1[e] + b1[e] )
// 128x128x8 tile, 256 threads, 8x8 micro-tile
__global__ __launch_bounds__(256)
void gemm1_kernel(const float* __restrict__ x,
                  const float* __restrict__ W1,
                  const float* __restrict__ b1) {
    __shared__ float As[8 * 128];   // transposed: As[k][row]
    __shared__ float Bs[8 * 128];   // Bs[k][col]

    int e   = blockIdx.z;
    int cnt = g_count[e];
    int m0  = blockIdx.y * 128;
    if (m0 >= cnt) return;
    int n0  = blockIdx.x * 128;
    int off = g_off[e];

    const float* W = W1 + (size_t)e * D_MODEL * D_FF;
    int tid = threadIdx.x;
    int tx = tid & 15, ty = tid >> 4;

    // A staging: one float4 per thread
    int aRow = tid >> 1;
    int aK4  = (tid & 1) * 4;
    int rcl  = min(m0 + aRow, cnt - 1);
    const float* aPtr = x + (size_t)g_rows[e * T_TOK + rcl] * D_MODEL + aK4;
    // B staging: one float4 per thread
    int bK = tid >> 5;
    int bN = (tid & 31) * 4;
    const float* bPtr = W + (size_t)bK * D_FF + n0 + bN;

    float c[8][8];
#pragma unroll
    for (int i = 0; i < 8; i++)
#pragma unroll
        for (int j = 0; j < 8; j++) c[i][j] = 0.f;

    for (int k0 = 0; k0 < D_MODEL; k0 += 8) {
        float4 av = *(const float4*)(aPtr + k0);
        float4 bv = *(const float4*)(bPtr + (size_t)k0 * D_FF);
        As[(aK4 + 0) * 128 + aRow] = av.x;
        As[(aK4 + 1) * 128 + aRow] = av.y;
        As[(aK4 + 2) * 128 + aRow] = av.z;
        As[(aK4 + 3) * 128 + aRow] = av.w;
        *(float4*)(Bs + bK * 128 + bN) = bv;
        __syncthreads();
#pragma unroll
        for (int kk = 0; kk < 8; kk++) {
            float4 a0 = *(const float4*)(As + kk * 128 + ty * 4);
            float4 a1 = *(const float4*)(As + kk * 128 + 64 + ty * 4);
            float4 b0 = *(const float4*)(Bs + kk * 128 + tx * 4);
            float4 b1v = *(const float4*)(Bs + kk * 128 + 64 + tx * 4);
            float ar[8] = {a0.x, a0.y, a0.z, a0.w, a1.x, a1.y, a1.z, a1.w};
            float br[8] = {b0.x, b0.y, b0.z, b0.w, b1v.x, b1v.y, b1v.z, b1v.w};
#pragma unroll
            for (int i = 0; i < 8; i++)
#pragma unroll
                for (int j = 0; j < 8; j++)
                    c[i][j] += ar[i] * br[j];
        }
        __syncthreads();
    }

    float bb[8];
#pragma unroll
    for (int j = 0; j < 8; j++) {
        int col = n0 + ((j < 4) ? tx * 4 + j : 64 + tx * 4 + (j - 4));
        bb[j] = b1[(size_t)e * D_FF + col];
    }
#pragma unroll
    for (int i = 0; i < 8; i++) {
        int r = m0 + ((i < 4) ? ty * 4 + i : 64 + ty * 4 + (i - 4));
        if (r < cnt) {
            float* hp = g_H + (size_t)(off + r) * D_FF + n0;
#pragma unroll
            for (int j = 0; j < 8; j++) {
                int col = (j < 4) ? tx * 4 + j : 64 + tx * 4 + (j - 4);
                float v = c[i][j] + bb[j];
                hp[col] = v > 0.f ? v : 0.f;
            }
        }
    }
}

// ---------------------------------------------------------------------------
// Pass B:  out[token] += gate * ( H @ W2[e] + b2[e] )
__global__ __launch_bounds__(256)
void gemm2_kernel(const float* __restrict__ W2,
                  const float* __restrict__ b2,
                  float* __restrict__ out) {
    __shared__ float As[8 * 128];
    __shared__ float Bs[8 * 128];

    int e   = blockIdx.z;
    int cnt = g_count[e];
    int m0  = blockIdx.y * 128;
    if (m0 >= cnt) return;
    int n0  = blockIdx.x * 128;
    int off = g_off[e];

    const float* W = W2 + (size_t)e * D_FF * D_MODEL;
    int tid = threadIdx.x;
    int tx = tid & 15, ty = tid >> 4;

    int aRow = tid >> 1;
    int aK4  = (tid & 1) * 4;
    const float* aPtr = g_H + (size_t)(off + m0 + aRow) * D_FF + aK4;
    int bK = tid >> 5;
    int bN = (tid & 31) * 4;
    const float* bPtr = W + (size_t)bK * D_MODEL + n0 + bN;

    float c[8][8];
#pragma unroll
    for (int i = 0; i < 8; i++)
#pragma unroll
        for (int j = 0; j < 8; j++) c[i][j] = 0.f;

    for (int k0 = 0; k0 < D_FF; k0 += 8) {
        float4 av = *(const float4*)(aPtr + k0);
        float4 bv = *(const float4*)(bPtr + (size_t)k0 * D_MODEL);
        As[(aK4 + 0) * 128 + aRow] = av.x;
        As[(aK4 + 1) * 128 + aRow] = av.y;
        As[(aK4 + 2) * 128 + aRow] = av.z;
        As[(aK4 + 3) * 128 + aRow] = av.w;
        *(float4*)(Bs + bK * 128 + bN) = bv;
        __syncthreads();
#pragma unroll
        for (int kk = 0; kk < 8; kk++) {
            float4 a0 = *(const float4*)(As + kk * 128 + ty * 4);
            float4 a1 = *(const float4*)(As + kk * 128 + 64 + ty * 4);
            float4 b0 = *(const float4*)(Bs + kk * 128 + tx * 4);
            float4 b1v = *(const float4*)(Bs + kk * 128 + 64 + tx * 4);
            float ar[8] = {a0.x, a0.y, a0.z, a0.w, a1.x, a1.y, a1.z, a1.w};
            float br[8] = {b0.x, b0.y, b0.z, b0.w, b1v.x, b1v.y, b1v.z, b1v.w};
#pragma unroll
            for (int i = 0; i < 8; i++)
#pragma unroll
                for (int j = 0; j < 8; j++)
                    c[i][j] += ar[i] * br[j];
        }
        __syncthreads();
    }

    float bb[8];
#pragma unroll
    for (int j = 0; j < 8; j++) {
        int col = n0 + ((j < 4) ? tx * 4 + j : 64 + tx * 4 + (j - 4));
        bb[j] = b2[(size_t)e * D_MODEL + col];
    }
#pragma unroll
    for (int i = 0; i < 8; i++) {
        int r = m0 + ((i < 4) ? ty * 4 + i : 64 + ty * 4 + (i - 4));
        if (r < cnt) {
            int   t = g_rows[e * T_TOK + r];
            float g = g_gate[e * T_TOK + r];
            float* op = out + (size_t)t * D_MODEL + n0;
#pragma unroll
            for (int j = 0; j < 8; j++) {
                int col = (j < 4) ? tx * 4 + j : 64 + tx * 4 + (j - 4);
                atomicAdd(op + col, g * (c[i][j] + bb[j]));
            }
        }
    }
}

// ---------------------------------------------------------------------------
extern "C" void kernel_launch(void* const* d_in, const int* in_sizes, int n_in,
                              void* d_out, int out_size) {
    const float* x  = (const float*)d_in[0];
    const float* Wr = (const float*)d_in[1];
    const float* W1 = (const float*)d_in[2];
    const float* b1 = (const float*)d_in[3];
    const float* W2 = (const float*)d_in[4];
    const float* b2 = (const float*)d_in[5];
    float* out = (float*)d_out;

    cudaMemsetAsync(out, 0, (size_t)out_size * sizeof(float));
    zero_counts_kernel<<<1, 32>>>();
    router_kernel<<<T_TOK / 8, 256>>>(x, Wr);
    offsets_kernel<<<1, 1>>>();

    dim3 g1(D_FF / 128, T_TOK / 128, N_EXP);
    gemm1_kernel<<<g1, 256>>>(x, W1, b1);
    dim3 g2(D_MODEL / 128, T_TOK / 128, N_EXP);
    gemm2_kernel<<<g2, 256>>>(W2, b2, out);
}

// round 3
// speedup vs baseline: 2.0417x; 2.0417x over previous
#include <cuda_runtime.h>
#include <cuda_bf16.h>
#include <math.h>
#include <stdint.h>

#define D_MODEL 1024
#define D_FF    4096
#define N_EXP   8
#define T_TOK   4096
#define XG_ROWS 9216          // 8192 + 8*128 padding
#define MAX_TILES 72

// ---- scratch (__device__ globals; no cudaMalloc allowed) --------------------
__device__ int   g_count[N_EXP];
__device__ int   g_off[N_EXP + 1];
__device__ int   g_rows[N_EXP * T_TOK];
__device__ float g_gate[N_EXP * T_TOK];
__device__ int   g_tileE[MAX_TILES];
__device__ int   g_tileM[MAX_TILES];
__device__ int   g_ntiles;
__device__ int   g_stok[XG_ROWS];
__device__ float g_sgate[XG_ROWS];

__device__ __nv_bfloat16 g_Xg_hi[(size_t)XG_ROWS * D_MODEL];
__device__ __nv_bfloat16 g_Xg_lo[(size_t)XG_ROWS * D_MODEL];
__device__ __nv_bfloat16 g_W1T_hi[(size_t)N_EXP * D_FF * D_MODEL];
__device__ __nv_bfloat16 g_W1T_lo[(size_t)N_EXP * D_FF * D_MODEL];
__device__ __nv_bfloat16 g_W2T_hi[(size_t)N_EXP * D_MODEL * D_FF];
__device__ __nv_bfloat16 g_W2T_lo[(size_t)N_EXP * D_MODEL * D_FF];
__device__ __nv_bfloat16 g_H_hi[(size_t)XG_ROWS * D_FF];
__device__ __nv_bfloat16 g_H_lo[(size_t)XG_ROWS * D_FF];

// ---- helpers ----------------------------------------------------------------
#define SWZ(o) ((o) ^ (((o) >> 3) & 0x70))

__device__ __forceinline__ uint32_t smem_u32(const void* p) {
    uint32_t a;
    asm("{ .reg .u64 t; cvta.to.shared.u64 t, %1; cvt.u32.u64 %0, t; }"
        : "=r"(a) : "l"(p));
    return a;
}
__device__ __forceinline__ void cp16(uint32_t dst, const void* src) {
    asm volatile("cp.async.cg.shared.global [%0], [%1], 16;"
                 :: "r"(dst), "l"(src) : "memory");
}
__device__ __forceinline__ void ldsm4(uint32_t* r, uint32_t addr) {
    asm volatile("ldmatrix.sync.aligned.m8n8.x4.shared.b16 {%0,%1,%2,%3}, [%4];"
                 : "=r"(r[0]), "=r"(r[1]), "=r"(r[2]), "=r"(r[3]) : "r"(addr));
}
__device__ __forceinline__ void mma_bf16(float* d, const uint32_t* a, const uint32_t* b) {
    asm volatile("mma.sync.aligned.m16n8k16.row.col.f32.bf16.bf16.f32 "
        "{%0,%1,%2,%3}, {%4,%5,%6,%7}, {%8,%9}, {%0,%1,%2,%3};"
        : "+f"(d[0]), "+f"(d[1]), "+f"(d[2]), "+f"(d[3])
        : "r"(a[0]), "r"(a[1]), "r"(a[2]), "r"(a[3]), "r"(b[0]), "r"(b[1]));
}
__device__ __forceinline__ void split2(float v, __nv_bfloat16& h, __nv_bfloat16& l) {
    h = __float2bfloat16(v);
    l = __float2bfloat16(v - __bfloat162float(h));
}

// ---- routing ----------------------------------------------------------------
__global__ void zero_counts_kernel() {
    if (threadIdx.x < N_EXP) g_count[threadIdx.x] = 0;
}

__global__ void router_kernel(const float* __restrict__ x,
                              const float* __restrict__ Wr) {
    int tok  = (blockIdx.x * blockDim.x + threadIdx.x) >> 5;
    int lane = threadIdx.x & 31;
    if (tok >= T_TOK) return;
    const float* xr = x + (size_t)tok * D_MODEL;
    float acc[N_EXP];
#pragma unroll
    for (int e = 0; e < N_EXP; e++) acc[e] = 0.f;
    for (int d = lane; d < D_MODEL; d += 32) {
        float xv = xr[d];
        float4 w0 = *(const float4*)(Wr + (size_t)d * N_EXP);
        float4 w1 = *(const float4*)(Wr + (size_t)d * N_EXP + 4);
        acc[0] += xv * w0.x; acc[1] += xv * w0.y;
        acc[2] += xv * w0.z; acc[3] += xv * w0.w;
        acc[4] += xv * w1.x; acc[5] += xv * w1.y;
        acc[6] += xv * w1.z; acc[7] += xv * w1.w;
    }
#pragma unroll
    for (int e = 0; e < N_EXP; e++)
#pragma unroll
        for (int o = 16; o > 0; o >>= 1)
            acc[e] += __shfl_xor_sync(0xffffffffu, acc[e], o);
    if (lane == 0) {
        int e1 = 0; float l1 = acc[0];
#pragma unroll
        for (int e = 1; e < N_EXP; e++)
            if (acc[e] > l1) { l1 = acc[e]; e1 = e; }
        int e2 = (e1 == 0) ? 1 : 0; float l2 = acc[e2];
#pragma unroll
        for (int e = 0; e < N_EXP; e++)
            if (e != e1 && acc[e] > l2) { l2 = acc[e]; e2 = e; }
        float g1 = 1.f / (1.f + expf(l2 - l1));
        float g2 = 1.f - g1;
        int p1 = atomicAdd(&g_count[e1], 1);
        g_rows[e1 * T_TOK + p1] = tok; g_gate[e1 * T_TOK + p1] = g1;
        int p2 = atomicAdd(&g_count[e2], 1);
        g_rows[e2 * T_TOK + p2] = tok; g_gate[e2 * T_TOK + p2] = g2;
    }
}

__global__ void offsets_kernel() {
    if (threadIdx.x != 0) return;
    int s = 0, t = 0;
    for (int e = 0; e < N_EXP; e++) {
        g_off[e] = s;
        int ct = (g_count[e] + 127) >> 7;
        for (int m = 0; m < ct; m++) { g_tileE[t] = e; g_tileM[t] = m << 7; t++; }
        s += ct << 7;
    }
    g_off[N_EXP] = s;
    g_ntiles = t;
}

// gather tokens to padded layout; split fp32 -> bf16 hi/lo; zero pad rows
__global__ void gather_split_x(const float* __restrict__ x) {
    int r = blockIdx.x;
    if (r >= g_off[N_EXP]) return;
    int e = 0;
#pragma unroll
    for (int k = 1; k < N_EXP; k++) if (r >= g_off[k]) e = k;
    int i = r - g_off[e];
    int tok = (i < g_count[e]) ? g_rows[e * T_TOK + i] : -1;
    if (threadIdx.x == 0) {
        g_stok[r]  = tok;
        g_sgate[r] = (tok >= 0) ? g_gate[e * T_TOK + i] : 0.f;
    }
    size_t base = (size_t)r * D_MODEL;
    if (tok < 0) {
        __nv_bfloat162 z; z.x = __float2bfloat16(0.f); z.y = z.x;
        for (int c = threadIdx.x; c < D_MODEL / 2; c += blockDim.x) {
            *(__nv_bfloat162*)(g_Xg_hi + base + 2 * c) = z;
            *(__nv_bfloat162*)(g_Xg_lo + base + 2 * c) = z;
        }
        return;
    }
    const float2* xp = (const float2*)(x + (size_t)tok * D_MODEL);
    for (int c = threadIdx.x; c < D_MODEL / 2; c += blockDim.x) {
        float2 v = xp[c];
        __nv_bfloat162 h, l;
        split2(v.x, h.x, l.x);
        split2(v.y, h.y, l.y);
        *(__nv_bfloat162*)(g_Xg_hi + base + 2 * c) = h;
        *(__nv_bfloat162*)(g_Xg_lo + base + 2 * c) = l;
    }
}

// transpose + split:  W[e][K][N] fp32 -> WT_hi/lo[e][N][K] bf16
__global__ void transpose_split(const float* __restrict__ W,
                                __nv_bfloat16* __restrict__ hi,
                                __nv_bfloat16* __restrict__ lo,
                                int K, int N) {
    __shared__ float t[32][33];
    int e  = blockIdx.z;
    int k0 = blockIdx.y * 32, n0 = blockIdx.x * 32;
    const float* Wp = W + ((size_t)e * K + k0) * N + n0;
    for (int i = threadIdx.y; i < 32; i += 8)
        t[i][threadIdx.x] = Wp[(size_t)i * N + threadIdx.x];
    __syncthreads();
    size_t base = ((size_t)e * N + n0) * K + k0;
    for (int i = threadIdx.y; i < 32; i += 8) {
        float v = t[threadIdx.x][i];
        __nv_bfloat16 h, l;
        split2(v, h, l);
        hi[base + (size_t)i * K + threadIdx.x] = h;
        lo[base + (size_t)i * K + threadIdx.x] = l;
    }
}

// ---------------------------------------------------------------------------
// mma.sync GEMM: 128x128 tile, BK=64, 3-stage cp.async pipeline.
// D = Ahi*Bhi + Ahi*Blo + Alo*Bhi (fp32 acc).
// Stage layout (64 KB): A_hi 16K | A_lo 16K | B_hi 16K | B_lo 16K
static constexpr int STG_BYTES = 65536;
static constexpr int SMEM_GEMM = 3 * STG_BYTES;

#define LOAD_STAGE(s, ktile) do {                                              \
    uint32_t st_ = sb + (uint32_t)(s) * STG_BYTES;                             \
    int k0_ = (ktile) * 64;                                                    \
    _Pragma("unroll")                                                          \
    for (int i_ = 0; i_ < 4; i_++) {                                           \
        int idx_ = tid + i_ * 256;                                             \
        int r_  = idx_ >> 3;                                                   \
        int cb_ = (idx_ & 7) << 4;                                             \
        uint32_t sw_ = SWZ(r_ * 128 + cb_);                                    \
        size_t ga_ = ((size_t)(rowA0 + r_) * KTOT + k0_) * 2 + cb_;            \
        size_t gb_ = ((size_t)(bRow0 + r_) * KTOT + k0_) * 2 + cb_;            \
        cp16(st_ + sw_,         (const char*)Ah + ga_);                        \
        cp16(st_ + 16384 + sw_, (const char*)Al + ga_);                        \
        cp16(st_ + 32768 + sw_, (const char*)Bh + gb_);                        \
        cp16(st_ + 49152 + sw_, (const char*)Bl + gb_);                        \
    }                                                                          \
    asm volatile("cp.async.commit_group;" ::: "memory");                       \
} while (0)

template<int PASS>
__global__ void __launch_bounds__(256, 1)
gemm_mma(const __nv_bfloat16* __restrict__ Ah, const __nv_bfloat16* __restrict__ Al,
         const __nv_bfloat16* __restrict__ Bh, const __nv_bfloat16* __restrict__ Bl,
         const float* __restrict__ bias, float* __restrict__ out)
{
    constexpr int KTOT = (PASS == 0) ? D_MODEL : D_FF;
    constexpr int NTOT = (PASS == 0) ? D_FF : D_MODEL;
    constexpr int KIT  = KTOT / 64;

    int t = blockIdx.y;
    if (t >= g_ntiles) return;
    int e     = g_tileE[t];
    int rowA0 = g_off[e] + g_tileM[t];
    int n0    = blockIdx.x * 128;
    int bRow0 = e * NTOT + n0;

    extern __shared__ char smem[];
    uint32_t sb = smem_u32(smem);

    int tid = threadIdx.x;
    int wid = tid >> 5, lane = tid & 31;
    int wm = wid >> 2, wn = wid & 3;       // warp tile: rows wm*64, cols wn*32

    float acc[4][4][4];
#pragma unroll
    for (int a = 0; a < 4; a++)
#pragma unroll
        for (int b = 0; b < 4; b++)
#pragma unroll
            for (int c = 0; c < 4; c++) acc[a][b][c] = 0.f;

    LOAD_STAGE(0, 0);
    LOAD_STAGE(1, 1);

    for (int kt = 0; kt < KIT; kt++) {
        asm volatile("cp.async.wait_group 1;" ::: "memory");
        __syncthreads();
        int s = kt % 3;
        uint32_t sA = sb + (uint32_t)s * STG_BYTES;
        uint32_t sB = sA + 32768;
#pragma unroll
        for (int k16 = 0; k16 < 4; k16++) {
            uint32_t a_h[4][4], a_l[4][4], b_h[2][4], b_l[2][4];
#pragma unroll
            for (int mt = 0; mt < 4; mt++) {
                uint32_t ad = sA + SWZ((wm * 64 + mt * 16 + (lane & 15)) * 128
                                       + k16 * 32 + (lane >> 4) * 16);
                ldsm4(a_h[mt], ad);
                ldsm4(a_l[mt], ad + 16384);
            }
#pragma unroll
            for (int nt = 0; nt < 2; nt++) {
                uint32_t bd = sB + SWZ((wn * 32 + nt * 16 + (lane & 15)) * 128
                                       + k16 * 32 + (lane >> 4) * 16);
                ldsm4(b_h[nt], bd);
                ldsm4(b_l[nt], bd + 16384);
            }
#pragma unroll
            for (int mt = 0; mt < 4; mt++)
#pragma unroll
                for (int n8 = 0; n8 < 4; n8++) {
                    int nt = n8 >> 1, hf = n8 & 1;
                    uint32_t bh[2] = { b_h[nt][hf], b_h[nt][2 + hf] };
                    uint32_t bl[2] = { b_l[nt][hf], b_l[nt][2 + hf] };
                    mma_bf16(acc[mt][n8], a_h[mt], bh);
                    mma_bf16(acc[mt][n8], a_h[mt], bl);
                    mma_bf16(acc[mt][n8], a_l[mt], bh);
                }
        }
        if (kt + 2 < KIT) { LOAD_STAGE((kt + 2) % 3, kt + 2); }
        else asm volatile("cp.async.commit_group;" ::: "memory");
    }

    // ---- epilogue ----
    const float* bp = bias + (size_t)e * NTOT;
#pragma unroll
    for (int mt = 0; mt < 4; mt++) {
        int r0 = wm * 64 + mt * 16 + (lane >> 2);
#pragma unroll
        for (int n8 = 0; n8 < 4; n8++) {
            int cg = n0 + wn * 32 + n8 * 8 + (lane & 3) * 2;
            float* a = acc[mt][n8];
            float bb0 = bp[cg], bb1 = bp[cg + 1];
            int row = rowA0 + r0;
            if (PASS == 0) {
                float v0 = fmaxf(a[0] + bb0, 0.f), v1 = fmaxf(a[1] + bb1, 0.f);
                float v2 = fmaxf(a[2] + bb0, 0.f), v3 = fmaxf(a[3] + bb1, 0.f);
                __nv_bfloat162 h, l;
                split2(v0, h.x, l.x); split2(v1, h.y, l.y);
                *(__nv_bfloat162*)(g_H_hi + (size_t)row * D_FF + cg) = h;
                *(__nv_bfloat162*)(g_H_lo + (size_t)row * D_FF + cg) = l;
                split2(v2, h.x, l.x); split2(v3, h.y, l.y);
                *(__nv_bfloat162*)(g_H_hi + (size_t)(row + 8) * D_FF + cg) = h;
                *(__nv_bfloat162*)(g_H_lo + (size_t)(row + 8) * D_FF + cg) = l;
            } else {
                int tok0 = g_stok[row], tok1 = g_stok[row + 8];
                if (tok0 >= 0) {
                    float g = g_sgate[row];
                    atomicAdd(out + (size_t)tok0 * D_MODEL + cg,     g * (a[0] + bb0));
                    atomicAdd(out + (size_t)tok0 * D_MODEL + cg + 1, g * (a[1] + bb1));
                }
                if (tok1 >= 0) {
                    float g = g_sgate[row + 8];
                    atomicAdd(out + (size_t)tok1 * D_MODEL + cg,     g * (a[2] + bb0));
                    atomicAdd(out + (size_t)tok1 * D_MODEL + cg + 1, g * (a[3] + bb1));
                }
            }
        }
    }
}

// ---------------------------------------------------------------------------
extern "C" void kernel_launch(void* const* d_in, const int* in_sizes, int n_in,
                              void* d_out, int out_size) {
    const float* x  = (const float*)d_in[0];
    const float* Wr = (const float*)d_in[1];
    const float* W1 = (const float*)d_in[2];
    const float* b1 = (const float*)d_in[3];
    const float* W2 = (const float*)d_in[4];
    const float* b2 = (const float*)d_in[5];
    float* out = (float*)d_out;

    void *pXh, *pXl, *pW1h, *pW1l, *pW2h, *pW2l, *pHh, *pHl;
    cudaGetSymbolAddress(&pXh,  g_Xg_hi);  cudaGetSymbolAddress(&pXl,  g_Xg_lo);
    cudaGetSymbolAddress(&pW1h, g_W1T_hi); cudaGetSymbolAddress(&pW1l, g_W1T_lo);
    cudaGetSymbolAddress(&pW2h, g_W2T_hi); cudaGetSymbolAddress(&pW2l, g_W2T_lo);
    cudaGetSymbolAddress(&pHh,  g_H_hi);   cudaGetSymbolAddress(&pHl,  g_H_lo);

    cudaFuncSetAttribute(gemm_mma<0>, cudaFuncAttributeMaxDynamicSharedMemorySize, SMEM_GEMM);
    cudaFuncSetAttribute(gemm_mma<1>, cudaFuncAttributeMaxDynamicSharedMemorySize, SMEM_GEMM);

    cudaMemsetAsync(out, 0, (size_t)out_size * sizeof(float));
    zero_counts_kernel<<<1, 32>>>();
    router_kernel<<<T_TOK / 8, 256>>>(x, Wr);
    offsets_kernel<<<1, 1>>>();

    dim3 tb(32, 8);
    transpose_split<<<dim3(D_FF / 32, D_MODEL / 32, N_EXP), tb>>>(
        W1, (__nv_bfloat16*)pW1h, (__nv_bfloat16*)pW1l, D_MODEL, D_FF);
    transpose_split<<<dim3(D_MODEL / 32, D_FF / 32, N_EXP), tb>>>(
        W2, (__nv_bfloat16*)pW2h, (__nv_bfloat16*)pW2l, D_FF, D_MODEL);
    gather_split_x<<<XG_ROWS, 256>>>(x);

    gemm_mma<0><<<dim3(D_FF / 128, MAX_TILES), 256, SMEM_GEMM>>>(
        (const __nv_bfloat16*)pXh, (const __nv_bfloat16*)pXl,
        (const __nv_bfloat16*)pW1h, (const __nv_bfloat16*)pW1l, b1, out);
    gemm_mma<1><<<dim3(D_MODEL / 128, MAX_TILES), 256, SMEM_GEMM>>>(
        (const __nv_bfloat16*)pHh, (const __nv_bfloat16*)pHl,
        (const __nv_bfloat16*)pW2h, (const __nv_bfloat16*)pW2l, b2, out);
}